// round 15
// baseline (speedup 1.0000x reference)
#include <cuda_runtime.h>

#define NP 262144
#define GRIDW 256
#define NUM_CELLS (GRIDW*GRIDW)
#define KSLOT 32
#define CAP 32
#define MAXN 64
#define FULLM 0xffffffffu

// ---------------- scratch (device globals) ----------------------------------
__device__ float    g_partH[256];
__device__ float    g_partX[256];
__device__ float    g_partY[256];
__device__ int      g_cellCount[NUM_CELLS + 1];
__device__ float4   g_cellListP[NUM_CELLS * CAP];       // {bits(idx), x, y, pad}
__device__ int      g_tabCnt[NUM_CELLS + 1];
__device__ float4   g_tab[(NUM_CELLS + 1) * KSLOT];     // {bits(idx), x, y, pad}
__device__ float2   g_aux[NP];                          // {t = d2 threshold, rh = 1/h}

// ------- kernel 1: zero counts + per-block partial reductions ---------------
__global__ void initRedK(const float* __restrict__ pos, const float* __restrict__ sup) {
    int tid = blockIdx.x * blockDim.x + threadIdx.x;
    for (int c = tid; c <= NUM_CELLS; c += gridDim.x * blockDim.x)
        g_cellCount[c] = 0;
    if (tid == 0) g_tabCnt[NUM_CELLS] = 0;   // sentinel cell: always empty

    __shared__ float sH[256], sX[256], sY[256];
    float h = 0.0f, x = __int_as_float(0x7f800000), y = __int_as_float(0x7f800000);
    for (int i = tid; i < NP; i += gridDim.x * blockDim.x) {
        h = fmaxf(h, sup[i]);
        float2 p = ((const float2*)pos)[i];
        x = fminf(x, p.x);
        y = fminf(y, p.y);
    }
    int t = threadIdx.x;
    sH[t] = h; sX[t] = x; sY[t] = y;
    __syncthreads();
    for (int s = 128; s > 0; s >>= 1) {
        if (t < s) {
            sH[t] = fmaxf(sH[t], sH[t + s]);
            sX[t] = fminf(sX[t], sX[t + s]);
            sY[t] = fminf(sY[t], sY[t + s]);
        }
        __syncthreads();
    }
    if (t == 0) {
        g_partH[blockIdx.x] = sH[0];
        g_partX[blockIdx.x] = sX[0];
        g_partY[blockIdx.x] = sY[0];
    }
}

// ------- kernel 2: combine partials + bin particles + per-particle aux ------
__global__ void binK(const float* __restrict__ pos, const float* __restrict__ sup) {
    __shared__ float sH[256], sX[256], sY[256];
    int t = threadIdx.x;
    sH[t] = g_partH[t]; sX[t] = g_partX[t]; sY[t] = g_partY[t];
    __syncthreads();
    for (int s = 128; s > 0; s >>= 1) {
        if (t < s) {
            sH[t] = fmaxf(sH[t], sH[t + s]);
            sX[t] = fminf(sX[t], sX[t + s]);
            sY[t] = fminf(sY[t], sY[t + s]);
        }
        __syncthreads();
    }
    float hM = sH[0];
    float qx = sX[0] - hM;
    float qy = sY[0] - hM;

    int i = blockIdx.x * blockDim.x + threadIdx.x;
    if (i >= NP) return;
    float2 p = ((const float2*)pos)[i];
    int ix = (int)ceilf((p.x - qx) / hM);
    int iy = (int)ceilf((p.y - qy) / hM);
    ix = min(max(ix, 0), GRIDW - 1);
    iy = min(max(iy, 0), GRIDW - 1);
    int lin = ix + GRIDW * iy;
    int slot = atomicAdd(&g_cellCount[lin], 1);
    if (slot < CAP)
        g_cellListP[lin * CAP + slot] = make_float4(__int_as_float(i), p.x, p.y, 0.0f);

    // ---- per-particle: t = largest float with fl(sqrt(t)) <= h  (exact) ----
    float h = sup[i];
    float u = __fmul_rn(h, h);
    if (__fsqrt_rn(u) > h) u = __int_as_float(__float_as_int(u) - 1);
    if (__fsqrt_rn(u) > h) u = __int_as_float(__float_as_int(u) - 1);
    if (__fsqrt_rn(u) > h) u = __int_as_float(__float_as_int(u) - 1);
    float un = __int_as_float(__float_as_int(u) + 1);
    if (__fsqrt_rn(un) <= h) {
        u = un; un = __int_as_float(__float_as_int(u) + 1);
        if (__fsqrt_rn(un) <= h) {
            u = un; un = __int_as_float(__float_as_int(u) + 1);
            if (__fsqrt_rn(un) <= h) u = un;
        }
    }
    g_aux[i] = make_float2(u, __frcp_rn(h));
}

// ------- kernel 3: rank sort, TWO cells per warp (2x MLP on load chain) -----
__global__ void sortK() {
    int base = ((blockIdx.x * blockDim.x + threadIdx.x) >> 5) * 2;
    if (base >= NUM_CELLS) return;
    int lane = threadIdx.x & 31;
    int w0 = base, w1 = base + 1;

    int m0 = min(g_cellCount[w0], KSLOT);
    int m1 = min(g_cellCount[w1], KSLOT);

    float4 e0 = make_float4(0.f, 0.f, 0.f, 0.f);
    float4 e1 = make_float4(0.f, 0.f, 0.f, 0.f);
    int idx0 = 0x7fffffff, idx1 = 0x7fffffff;
    if (lane < m0) { e0 = g_cellListP[w0 * CAP + lane]; idx0 = __float_as_int(e0.x); }
    if (lane < m1) { e1 = g_cellListP[w1 * CAP + lane]; idx1 = __float_as_int(e1.x); }

    int r0 = 0, r1 = 0;
    for (int j = 0; j < m0; j++) r0 += (__shfl_sync(FULLM, idx0, j) < idx0);
    for (int j = 0; j < m1; j++) r1 += (__shfl_sync(FULLM, idx1, j) < idx1);

    if (lane == 0) { g_tabCnt[w0] = m0; g_tabCnt[w1] = m1; }
    if (lane < m0) g_tab[w0 * KSLOT + r0] = e0;
    if (lane < m1) g_tab[w1 * KSLOT + r1] = e1;
}

__device__ __forceinline__ float sqrt_approx(float x) {
    float r;
    asm("sqrt.approx.f32 %0, %1;" : "=f"(r) : "f"(x));
    return r;
}

// ------- kernel 4: PAIR-of-cells per warp neighbor search --------------------
// Cells w, w+1 share a 12-column union stencil (dx in {-1..2} x dy in {-1..1},
// lex order on lanes 0..11). Lanes 0..8 = w's 9 ref-ordered columns (t < P9);
// lanes 3..11 = (w+1)'s (P3 <= t < Tu). Lex order preserves each cell's
// per-query candidate order => outputs bit-identical to the 1-cell version.
__global__ void searchK(float* __restrict__ out) {
    int pair = (blockIdx.x * blockDim.x + threadIdx.x) >> 5;
    if (pair >= NUM_CELLS / 2) return;
    int w = pair * 2;
    int lane = threadIdx.x & 31;
    unsigned below = (1u << lane) - 1u;

    // ---- 12-column stencil setup (once per pair) ----
    int l3 = lane / 3;
    int dxl = l3 - 1;
    int dyl = lane - l3 * 3 - 1;
    int ccl = min(max(w + dxl + GRIDW * dyl, 0), NUM_CELLS);
    int m = (lane < 12) ? g_tabCnt[ccl] : 0;

    int incl = m;
#pragma unroll
    for (int d = 1; d < 16; d <<= 1) {
        int v = __shfl_up_sync(FULLM, incl, d);
        if (lane >= d) incl += v;
    }
    int pref = incl - m;
    int Tu = __shfl_sync(FULLM, incl, 11);

    int qA = __shfl_sync(FULLM, m, 4);    // center of w  = column (0,0)
    int qB = __shfl_sync(FULLM, m, 7);    // center of w+1 = column (1,0)
    if ((qA | qB) == 0) return;

    int P1  = __shfl_sync(FULLM, pref, 1);
    int P2  = __shfl_sync(FULLM, pref, 2);
    int P3  = __shfl_sync(FULLM, pref, 3);
    int P4  = __shfl_sync(FULLM, pref, 4);
    int P5  = __shfl_sync(FULLM, pref, 5);
    int P6  = __shfl_sync(FULLM, pref, 6);
    int P7  = __shfl_sync(FULLM, pref, 7);
    int P8  = __shfl_sync(FULLM, pref, 8);
    int P9  = __shfl_sync(FULLM, pref, 9);
    int P10 = __shfl_sync(FULLM, pref, 10);
    int P11 = __shfl_sync(FULLM, pref, 11);

    // ---- query data for both cells (parallel gathers) ----
    float4 qeA = make_float4(0.f, 0.f, 0.f, 0.f);
    float4 qeB = make_float4(0.f, 0.f, 0.f, 0.f);
    float tLA = 0.f, rhLA = 0.f, tLB = 0.f, rhLB = 0.f;
    int qidA = 0, qidB = 0;
    if (lane < qA) {
        qeA = g_cellListP[w * CAP + lane];
        qidA = __float_as_int(qeA.x);
        float2 aux = __ldg(&g_aux[qidA]);
        tLA = aux.x; rhLA = aux.y;
    }
    if (lane < qB) {
        qeB = g_cellListP[(w + 1) * CAP + lane];
        qidB = __float_as_int(qeB.x);
        float2 aux = __ldg(&g_aux[qidB]);
        tLB = aux.x; rhLB = aux.y;
    }

    // ---- preload union candidates (chunks 0,1 cover Tu <= 64) ----
    float4 e0 = make_float4(0.f, 0.f, 0.f, 0.f);
    float4 e1 = make_float4(0.f, 0.f, 0.f, 0.f);
    {
        int t = lane;
        int o = (t >= P1) + (t >= P2) + (t >= P3) + (t >= P4) + (t >= P5) +
                (t >= P6) + (t >= P7) + (t >= P8) + (t >= P9) + (t >= P10) + (t >= P11);
        int cc = __shfl_sync(FULLM, ccl, o);
        int po = __shfl_sync(FULLM, pref, o);
        if (t < Tu) e0 = g_tab[cc * KSLOT + (t - po)];
    }
    if (Tu > 32) {
        int t = lane + 32;
        int o = (t >= P1) + (t >= P2) + (t >= P3) + (t >= P4) + (t >= P5) +
                (t >= P6) + (t >= P7) + (t >= P8) + (t >= P9) + (t >= P10) + (t >= P11);
        int cc = __shfl_sync(FULLM, ccl, o);
        int po = __shfl_sync(FULLM, pref, o);
        if (t < Tu) e1 = g_tab[cc * KSLOT + (t - po)];
    }
    float n0 = (float)__float_as_int(e0.x);
    float n1 = (float)__float_as_int(e1.x);

    // per-lane validity for each cell's stencil within chunks
    bool actA0 = lane < P9;
    bool actA1 = (lane + 32) < P9;
    bool actB0 = (lane >= P3) && (lane < Tu);
    bool actB1 = ((lane + 32) >= P3) && ((lane + 32) < Tu);

    float* outN = out;                              // (N, 64) neighbor indices
    float* outC = out + (size_t)NP * MAXN;          // (N,)    counts
    float* outR = outC + NP;                        // (N, 64) radial

    // ================= cell A (= w) queries, candidates t in [0, P9) ========
    int myCntA = 0;
    for (int q = 0; q < qA; q++) {
        float px = __shfl_sync(FULLM, qeA.y, q);
        float py = __shfl_sync(FULLM, qeA.z, q);
        float tq = __shfl_sync(FULLM, tLA, q);
        float rh = __shfl_sync(FULLM, rhLA, q);
        int  qid = __shfl_sync(FULLM, qidA, q);
        int  rbase = qid << 6;
        float* pN = outN + rbase;
        float* pR = outR + rbase;

        int cnt;
        {
            float dx = __fsub_rn(e0.y, px);
            float dy = __fsub_rn(e0.z, py);
            float d2 = __fadd_rn(__fmul_rn(dx, dx), __fmul_rn(dy, dy));
            bool ok = actA0 && (d2 <= tq);
            unsigned bal = __ballot_sync(FULLM, ok);
            int slot = __popc(bal & below);
            if (ok) {
                __stcs(&pN[slot], n0);
                __stcs(&pR[slot], __fmul_rn(sqrt_approx(d2), rh));
            }
            cnt = __popc(bal);
        }
        if (Tu > 32) {
            float dx = __fsub_rn(e1.y, px);
            float dy = __fsub_rn(e1.z, py);
            float d2 = __fadd_rn(__fmul_rn(dx, dx), __fmul_rn(dy, dy));
            bool ok = actA1 && (d2 <= tq);
            unsigned bal = __ballot_sync(FULLM, ok);
            int slot = cnt + __popc(bal & below);
            if (ok) {
                __stcs(&pN[slot], n1);
                __stcs(&pR[slot], __fmul_rn(sqrt_approx(d2), rh));
            }
            cnt += __popc(bal);
        }
        // rare overflow: union beyond 64 candidates, A needs t < P9
        for (int tb = 64; tb < P9; tb += 32) {
            int t = tb + lane;
            bool act = t < P9;
            int o = (t >= P1) + (t >= P2) + (t >= P3) + (t >= P4) + (t >= P5) +
                    (t >= P6) + (t >= P7) + (t >= P8) + (t >= P9) + (t >= P10) + (t >= P11);
            int cc = __shfl_sync(FULLM, ccl, o);
            int po = __shfl_sync(FULLM, pref, o);
            float nidx = 0.0f, d2 = 0.0f;
            bool ok = false;
            if (act) {
                float4 e = g_tab[cc * KSLOT + (t - po)];
                float dx = __fsub_rn(e.y, px);
                float dy = __fsub_rn(e.z, py);
                d2 = __fadd_rn(__fmul_rn(dx, dx), __fmul_rn(dy, dy));
                nidx = (float)__float_as_int(e.x);
                ok = d2 <= tq;
            }
            unsigned bal = __ballot_sync(FULLM, ok);
            int slot = cnt + __popc(bal & below);
            if (ok && slot < MAXN) {
                __stcs(&pN[slot], nidx);
                __stcs(&pR[slot], __fmul_rn(sqrt_approx(d2), rh));
            }
            cnt += __popc(bal);
        }
        int start = min(cnt, MAXN);
        int k0 = start + lane;
        if (k0 < MAXN) { __stcs(&pN[k0], -1.0f); __stcs(&pR[k0], 0.0f); }
        int k1 = k0 + 32;
        if (k1 < MAXN) { __stcs(&pN[k1], -1.0f); __stcs(&pR[k1], 0.0f); }
        if (q == lane) myCntA = cnt;
    }
    if (lane < qA) __stcs(&outC[qidA], (float)myCntA);

    // ================= cell B (= w+1) queries, candidates t in [P3, Tu) =====
    int myCntB = 0;
    for (int q = 0; q < qB; q++) {
        float px = __shfl_sync(FULLM, qeB.y, q);
        float py = __shfl_sync(FULLM, qeB.z, q);
        float tq = __shfl_sync(FULLM, tLB, q);
        float rh = __shfl_sync(FULLM, rhLB, q);
        int  qid = __shfl_sync(FULLM, qidB, q);
        int  rbase = qid << 6;
        float* pN = outN + rbase;
        float* pR = outR + rbase;

        int cnt;
        {
            float dx = __fsub_rn(e0.y, px);
            float dy = __fsub_rn(e0.z, py);
            float d2 = __fadd_rn(__fmul_rn(dx, dx), __fmul_rn(dy, dy));
            bool ok = actB0 && (d2 <= tq);
            unsigned bal = __ballot_sync(FULLM, ok);
            int slot = __popc(bal & below);
            if (ok) {
                __stcs(&pN[slot], n0);
                __stcs(&pR[slot], __fmul_rn(sqrt_approx(d2), rh));
            }
            cnt = __popc(bal);
        }
        if (Tu > 32) {
            float dx = __fsub_rn(e1.y, px);
            float dy = __fsub_rn(e1.z, py);
            float d2 = __fadd_rn(__fmul_rn(dx, dx), __fmul_rn(dy, dy));
            bool ok = actB1 && (d2 <= tq);
            unsigned bal = __ballot_sync(FULLM, ok);
            int slot = cnt + __popc(bal & below);
            if (ok) {
                __stcs(&pN[slot], n1);
                __stcs(&pR[slot], __fmul_rn(sqrt_approx(d2), rh));
            }
            cnt += __popc(bal);
        }
        // rare overflow: B needs P3 <= t < Tu
        for (int tb = 64; tb < Tu; tb += 32) {
            int t = tb + lane;
            bool act = t < Tu;           // t >= 64 >= P3 always here
            int o = (t >= P1) + (t >= P2) + (t >= P3) + (t >= P4) + (t >= P5) +
                    (t >= P6) + (t >= P7) + (t >= P8) + (t >= P9) + (t >= P10) + (t >= P11);
            int cc = __shfl_sync(FULLM, ccl, o);
            int po = __shfl_sync(FULLM, pref, o);
            float nidx = 0.0f, d2 = 0.0f;
            bool ok = false;
            if (act) {
                float4 e = g_tab[cc * KSLOT + (t - po)];
                float dx = __fsub_rn(e.y, px);
                float dy = __fsub_rn(e.z, py);
                d2 = __fadd_rn(__fmul_rn(dx, dx), __fmul_rn(dy, dy));
                nidx = (float)__float_as_int(e.x);
                ok = d2 <= tq;
            }
            unsigned bal = __ballot_sync(FULLM, ok);
            int slot = cnt + __popc(bal & below);
            if (ok && slot < MAXN) {
                __stcs(&pN[slot], nidx);
                __stcs(&pR[slot], __fmul_rn(sqrt_approx(d2), rh));
            }
            cnt += __popc(bal);
        }
        int start = min(cnt, MAXN);
        int k0 = start + lane;
        if (k0 < MAXN) { __stcs(&pN[k0], -1.0f); __stcs(&pR[k0], 0.0f); }
        int k1 = k0 + 32;
        if (k1 < MAXN) { __stcs(&pN[k1], -1.0f); __stcs(&pR[k1], 0.0f); }
        if (q == lane) myCntB = cnt;
    }
    if (lane < qB) __stcs(&outC[qidB], (float)myCntB);
}

// ---------------- launch ------------------------------------------------------
extern "C" void kernel_launch(void* const* d_in, const int* in_sizes, int n_in,
                              void* d_out, int out_size) {
    const float* pos = (const float*)d_in[0];   // (N, 2) float32
    const float* sup = (const float*)d_in[1];   // (N,)   float32
    float* out = (float*)d_out;

    initRedK<<<256, 256>>>(pos, sup);
    binK<<<NP / 256, 256>>>(pos, sup);
    sortK<<<(NUM_CELLS / 2 * 32) / 256, 256>>>();
    searchK<<<(NUM_CELLS / 2 * 32) / 256, 256>>>(out);
}

// round 16
// speedup vs baseline: 1.1429x; 1.1429x over previous
#include <cuda_runtime.h>

#define NP 262144
#define GRIDW 256
#define NUM_CELLS (GRIDW*GRIDW)
#define KSLOT 32
#define CAP 32
#define MAXN 64
#define FULLM 0xffffffffu

// ---------------- scratch (device globals) ----------------------------------
__device__ float    g_partH[256];
__device__ float    g_partX[256];
__device__ float    g_partY[256];
__device__ int      g_cellCount[NUM_CELLS + 1];
__device__ float4   g_cellListP[NUM_CELLS * CAP];       // {bits(idx), x, y, tq}
__device__ int      g_tabCnt[NUM_CELLS + 1];
__device__ float4   g_tab[(NUM_CELLS + 1) * KSLOT];     // {bits(idx), x, y, tq}

// ------- kernel 1: zero counts + per-block partial reductions ---------------
__global__ void initRedK(const float* __restrict__ pos, const float* __restrict__ sup) {
    int tid = blockIdx.x * blockDim.x + threadIdx.x;
    for (int c = tid; c <= NUM_CELLS; c += gridDim.x * blockDim.x)
        g_cellCount[c] = 0;
    if (tid == 0) g_tabCnt[NUM_CELLS] = 0;   // sentinel cell: always empty

    __shared__ float sH[256], sX[256], sY[256];
    float h = 0.0f, x = __int_as_float(0x7f800000), y = __int_as_float(0x7f800000);
    for (int i = tid; i < NP; i += gridDim.x * blockDim.x) {
        h = fmaxf(h, sup[i]);
        float2 p = ((const float2*)pos)[i];
        x = fminf(x, p.x);
        y = fminf(y, p.y);
    }
    int t = threadIdx.x;
    sH[t] = h; sX[t] = x; sY[t] = y;
    __syncthreads();
    for (int s = 128; s > 0; s >>= 1) {
        if (t < s) {
            sH[t] = fmaxf(sH[t], sH[t + s]);
            sX[t] = fminf(sX[t], sX[t + s]);
            sY[t] = fminf(sY[t], sY[t + s]);
        }
        __syncthreads();
    }
    if (t == 0) {
        g_partH[blockIdx.x] = sH[0];
        g_partX[blockIdx.x] = sX[0];
        g_partY[blockIdx.x] = sY[0];
    }
}

// ------- kernel 2: combine partials + bin particles (tq fused into record) --
__global__ void binK(const float* __restrict__ pos, const float* __restrict__ sup) {
    __shared__ float sH[256], sX[256], sY[256];
    int t = threadIdx.x;
    sH[t] = g_partH[t]; sX[t] = g_partX[t]; sY[t] = g_partY[t];
    __syncthreads();
    for (int s = 128; s > 0; s >>= 1) {
        if (t < s) {
            sH[t] = fmaxf(sH[t], sH[t + s]);
            sX[t] = fminf(sX[t], sX[t + s]);
            sY[t] = fminf(sY[t], sY[t + s]);
        }
        __syncthreads();
    }
    float hM = sH[0];
    float qx = sX[0] - hM;
    float qy = sY[0] - hM;

    int i = blockIdx.x * blockDim.x + threadIdx.x;
    if (i >= NP) return;

    // ---- per-particle: u = largest float with fl(sqrt(u)) <= h  (exact) ----
    float h = sup[i];
    float u = __fmul_rn(h, h);
    if (__fsqrt_rn(u) > h) u = __int_as_float(__float_as_int(u) - 1);
    if (__fsqrt_rn(u) > h) u = __int_as_float(__float_as_int(u) - 1);
    if (__fsqrt_rn(u) > h) u = __int_as_float(__float_as_int(u) - 1);
    float un = __int_as_float(__float_as_int(u) + 1);
    if (__fsqrt_rn(un) <= h) {
        u = un; un = __int_as_float(__float_as_int(u) + 1);
        if (__fsqrt_rn(un) <= h) {
            u = un; un = __int_as_float(__float_as_int(u) + 1);
            if (__fsqrt_rn(un) <= h) u = un;
        }
    }

    float2 p = ((const float2*)pos)[i];
    int ix = (int)ceilf((p.x - qx) / hM);
    int iy = (int)ceilf((p.y - qy) / hM);
    ix = min(max(ix, 0), GRIDW - 1);
    iy = min(max(iy, 0), GRIDW - 1);
    int lin = ix + GRIDW * iy;
    int slot = atomicAdd(&g_cellCount[lin], 1);
    if (slot < CAP)
        g_cellListP[lin * CAP + slot] = make_float4(__int_as_float(i), p.x, p.y, u);
}

// ------- kernel 3: rank sort, FOUR cells per warp (4x MLP on load chain) ----
__global__ void sortK() {
    int base = ((blockIdx.x * blockDim.x + threadIdx.x) >> 5) * 4;
    if (base >= NUM_CELLS) return;
    int lane = threadIdx.x & 31;

    int m0 = min(g_cellCount[base + 0], KSLOT);
    int m1 = min(g_cellCount[base + 1], KSLOT);
    int m2 = min(g_cellCount[base + 2], KSLOT);
    int m3 = min(g_cellCount[base + 3], KSLOT);

    float4 e0, e1, e2, e3;
    int i0 = 0x7fffffff, i1 = 0x7fffffff, i2 = 0x7fffffff, i3 = 0x7fffffff;
    if (lane < m0) { e0 = g_cellListP[(base + 0) * CAP + lane]; i0 = __float_as_int(e0.x); }
    if (lane < m1) { e1 = g_cellListP[(base + 1) * CAP + lane]; i1 = __float_as_int(e1.x); }
    if (lane < m2) { e2 = g_cellListP[(base + 2) * CAP + lane]; i2 = __float_as_int(e2.x); }
    if (lane < m3) { e3 = g_cellListP[(base + 3) * CAP + lane]; i3 = __float_as_int(e3.x); }

    int r0 = 0, r1 = 0, r2 = 0, r3 = 0;
    for (int j = 0; j < m0; j++) r0 += (__shfl_sync(FULLM, i0, j) < i0);
    for (int j = 0; j < m1; j++) r1 += (__shfl_sync(FULLM, i1, j) < i1);
    for (int j = 0; j < m2; j++) r2 += (__shfl_sync(FULLM, i2, j) < i2);
    for (int j = 0; j < m3; j++) r3 += (__shfl_sync(FULLM, i3, j) < i3);

    if (lane == 0) {
        g_tabCnt[base + 0] = m0;
        g_tabCnt[base + 1] = m1;
        g_tabCnt[base + 2] = m2;
        g_tabCnt[base + 3] = m3;
    }
    if (lane < m0) g_tab[(base + 0) * KSLOT + r0] = e0;
    if (lane < m1) g_tab[(base + 1) * KSLOT + r1] = e1;
    if (lane < m2) g_tab[(base + 2) * KSLOT + r2] = e2;
    if (lane < m3) g_tab[(base + 3) * KSLOT + r3] = e3;
}

__device__ __forceinline__ float sqrt_approx(float x) {
    float r;
    asm("sqrt.approx.f32 %0, %1;" : "=f"(r) : "f"(x));
    return r;
}
__device__ __forceinline__ float rcp_approx(float x) {
    float r;
    asm("rcp.approx.f32 %0, %1;" : "=f"(r) : "f"(x));
    return r;
}

// ------- kernel 4: warp-per-cell neighbor search (R14 form, aux removed) ----
__global__ void searchK(float* __restrict__ out) {
    int w = (blockIdx.x * blockDim.x + threadIdx.x) >> 5;   // warp id = cell
    if (w >= NUM_CELLS) return;
    int lane = threadIdx.x & 31;

    // ---- stencil setup (once per cell) ----
    int c = NUM_CELLS, m = 0;
    if (lane < 9) {
        int dxo = lane / 3 - 1;
        int dyo = lane % 3 - 1;
        int cc = w + dxo + GRIDW * dyo;
        cc = min(max(cc, 0), NUM_CELLS);
        c = cc;
        m = g_tabCnt[cc];
    }
    int incl = m;
#pragma unroll
    for (int d = 1; d < 16; d <<= 1) {
        int v = __shfl_up_sync(FULLM, incl, d);
        if (lane >= d) incl += v;
    }
    int pref = incl - m;
    int T = __shfl_sync(FULLM, incl, 8);

    int qcnt = __shfl_sync(FULLM, m, 4);      // center cell = this cell's queries
    if (qcnt == 0) return;

    int p1 = __shfl_sync(FULLM, pref, 1);
    int p2 = __shfl_sync(FULLM, pref, 2);
    int p3 = __shfl_sync(FULLM, pref, 3);
    int p4 = __shfl_sync(FULLM, pref, 4);
    int p5 = __shfl_sync(FULLM, pref, 5);
    int p6 = __shfl_sync(FULLM, pref, 6);
    int p7 = __shfl_sync(FULLM, pref, 7);
    int p8 = __shfl_sync(FULLM, pref, 8);

    // ---- query data (record now carries tq in .w; no aux gather) ----
    float4 qe = make_float4(0.f, 0.f, 0.f, 0.f);
    int qidl = 0;
    if (lane < qcnt) {
        qe = g_cellListP[w * CAP + lane];
        qidl = __float_as_int(qe.x);
    }

    // ---- preload candidates (chunks 0,1 cover T <= 64) ----
    float4 e0 = make_float4(0.f, 0.f, 0.f, 0.f);
    float4 e1 = make_float4(0.f, 0.f, 0.f, 0.f);
    bool act0 = lane < T;
    {
        int t = lane;
        int o = (t >= p1) + (t >= p2) + (t >= p3) + (t >= p4) +
                (t >= p5) + (t >= p6) + (t >= p7) + (t >= p8);
        int cc = __shfl_sync(FULLM, c, o);
        int po = __shfl_sync(FULLM, pref, o);
        if (act0) e0 = g_tab[cc * KSLOT + (t - po)];
    }
    bool act1 = (lane + 32) < T;
    if (T > 32) {
        int t = lane + 32;
        int o = (t >= p1) + (t >= p2) + (t >= p3) + (t >= p4) +
                (t >= p5) + (t >= p6) + (t >= p7) + (t >= p8);
        int cc = __shfl_sync(FULLM, c, o);
        int po = __shfl_sync(FULLM, pref, o);
        if (act1) e1 = g_tab[cc * KSLOT + (t - po)];
    }
    float n0 = (float)__float_as_int(e0.x);
    float n1 = (float)__float_as_int(e1.x);

    float* outN = out;                              // (N, 64) neighbor indices
    float* outC = out + (size_t)NP * MAXN;          // (N,)    counts
    float* outR = outC + NP;                        // (N, 64) radial

    int myCnt = 0;                                  // this lane's query count

    // ---- per-query loop (4 broadcasts/query) ----
    for (int q = 0; q < qcnt; q++) {
        float px = __shfl_sync(FULLM, qe.y, q);
        float py = __shfl_sync(FULLM, qe.z, q);
        float tq = __shfl_sync(FULLM, qe.w, q);
        int  qid = __shfl_sync(FULLM, qidl, q);
        float rtq = rcp_approx(tq);                 // 1/h^2 (approx; radial only)
        int  rbase = qid << 6;                      // 32-bit row offset
        float* pN = outN + rbase;
        float* pR = outR + rbase;

        int cnt;
        // chunk 0
        {
            float dx = __fsub_rn(e0.y, px);
            float dy = __fsub_rn(e0.z, py);
            float d2 = __fadd_rn(__fmul_rn(dx, dx), __fmul_rn(dy, dy));
            bool ok = act0 && (d2 <= tq);           // exact selection
            unsigned bal = __ballot_sync(FULLM, ok);
            int slot = __popc(bal & ((1u << lane) - 1u));
            if (ok) {
                __stcs(&pN[slot], n0);
                __stcs(&pR[slot], sqrt_approx(__fmul_rn(d2, rtq)));
            }
            cnt = __popc(bal);
        }
        // chunk 1
        if (T > 32) {
            float dx = __fsub_rn(e1.y, px);
            float dy = __fsub_rn(e1.z, py);
            float d2 = __fadd_rn(__fmul_rn(dx, dx), __fmul_rn(dy, dy));
            bool ok = act1 && (d2 <= tq);
            unsigned bal = __ballot_sync(FULLM, ok);
            int slot = cnt + __popc(bal & ((1u << lane) - 1u));
            if (ok) {
                __stcs(&pN[slot], n1);
                __stcs(&pR[slot], sqrt_approx(__fmul_rn(d2, rtq)));
            }
            cnt += __popc(bal);
        }
        // rare: T > 64
        for (int tb = 64; tb < T; tb += 32) {
            int t = tb + lane;
            bool act = t < T;
            int o = (t >= p1) + (t >= p2) + (t >= p3) + (t >= p4) +
                    (t >= p5) + (t >= p6) + (t >= p7) + (t >= p8);
            int cc = __shfl_sync(FULLM, c, o);
            int po = __shfl_sync(FULLM, pref, o);
            float nidx = 0.0f, d2 = 0.0f;
            bool ok = false;
            if (act) {
                float4 e = g_tab[cc * KSLOT + (t - po)];
                float dx = __fsub_rn(e.y, px);
                float dy = __fsub_rn(e.z, py);
                d2 = __fadd_rn(__fmul_rn(dx, dx), __fmul_rn(dy, dy));
                nidx = (float)__float_as_int(e.x);
                ok = d2 <= tq;
            }
            unsigned bal = __ballot_sync(FULLM, ok);
            int slot = cnt + __popc(bal & ((1u << lane) - 1u));
            if (ok && slot < MAXN) {
                __stcs(&pN[slot], nidx);
                __stcs(&pR[slot], sqrt_approx(__fmul_rn(d2, rtq)));
            }
            cnt += __popc(bal);
        }
        // tail fill: unrolled two predicated steps (tail length <= 64)
        int start = min(cnt, MAXN);
        int k0 = start + lane;
        if (k0 < MAXN) {
            __stcs(&pN[k0], -1.0f);
            __stcs(&pR[k0], 0.0f);
        }
        int k1 = k0 + 32;
        if (k1 < MAXN) {
            __stcs(&pN[k1], -1.0f);
            __stcs(&pR[k1], 0.0f);
        }
        if (q == lane) myCnt = cnt;                 // defer count store
    }
    if (lane < qcnt) __stcs(&outC[qidl], (float)myCnt);
}

// ---------------- launch ------------------------------------------------------
extern "C" void kernel_launch(void* const* d_in, const int* in_sizes, int n_in,
                              void* d_out, int out_size) {
    const float* pos = (const float*)d_in[0];   // (N, 2) float32
    const float* sup = (const float*)d_in[1];   // (N,)   float32
    float* out = (float*)d_out;

    initRedK<<<256, 256>>>(pos, sup);
    binK<<<NP / 256, 256>>>(pos, sup);
    sortK<<<(NUM_CELLS / 4 * 32) / 256, 256>>>();
    searchK<<<(NUM_CELLS * 32) / 256, 256>>>(out);
}

// round 17
// speedup vs baseline: 1.2031x; 1.0527x over previous
#include <cuda_runtime.h>

#define NP 262144
#define GRIDW 256
#define NUM_CELLS (GRIDW*GRIDW)
#define KSLOT 32
#define CAP 32
#define MAXN 64
#define FULLM 0xffffffffu

// ---------------- scratch (device globals) ----------------------------------
__device__ float    g_partH[256];
__device__ float    g_partX[256];
__device__ float    g_partY[256];
__device__ int      g_cellCount[NUM_CELLS + 1];
__device__ float4   g_cellListP[NUM_CELLS * CAP];       // {bits(idx), x, y, pad}
__device__ int      g_tabCnt[NUM_CELLS + 1];
__device__ float4   g_tab[(NUM_CELLS + 1) * KSLOT];     // {bits(idx), x, y, pad}
__device__ float2   g_aux[NP];                          // {t = d2 threshold, rh = 1/h}

// ------- kernel 1: zero counts + per-block partial reductions ---------------
__global__ void initRedK(const float* __restrict__ pos, const float* __restrict__ sup) {
    int tid = blockIdx.x * blockDim.x + threadIdx.x;
    for (int c = tid; c <= NUM_CELLS; c += gridDim.x * blockDim.x)
        g_cellCount[c] = 0;
    if (tid == 0) g_tabCnt[NUM_CELLS] = 0;   // sentinel cell: always empty

    __shared__ float sH[256], sX[256], sY[256];
    float h = 0.0f, x = __int_as_float(0x7f800000), y = __int_as_float(0x7f800000);
    for (int i = tid; i < NP; i += gridDim.x * blockDim.x) {
        h = fmaxf(h, sup[i]);
        float2 p = ((const float2*)pos)[i];
        x = fminf(x, p.x);
        y = fminf(y, p.y);
    }
    int t = threadIdx.x;
    sH[t] = h; sX[t] = x; sY[t] = y;
    __syncthreads();
    for (int s = 128; s > 0; s >>= 1) {
        if (t < s) {
            sH[t] = fmaxf(sH[t], sH[t + s]);
            sX[t] = fminf(sX[t], sX[t + s]);
            sY[t] = fminf(sY[t], sY[t + s]);
        }
        __syncthreads();
    }
    if (t == 0) {
        g_partH[blockIdx.x] = sH[0];
        g_partX[blockIdx.x] = sX[0];
        g_partY[blockIdx.x] = sY[0];
    }
}

// ------- kernel 2: combine partials + bin particles + per-particle aux ------
__global__ void binK(const float* __restrict__ pos, const float* __restrict__ sup) {
    __shared__ float sH[256], sX[256], sY[256];
    int t = threadIdx.x;
    sH[t] = g_partH[t]; sX[t] = g_partX[t]; sY[t] = g_partY[t];
    __syncthreads();
    for (int s = 128; s > 0; s >>= 1) {
        if (t < s) {
            sH[t] = fmaxf(sH[t], sH[t + s]);
            sX[t] = fminf(sX[t], sX[t + s]);
            sY[t] = fminf(sY[t], sY[t + s]);
        }
        __syncthreads();
    }
    float hM = sH[0];
    float qx = sX[0] - hM;
    float qy = sY[0] - hM;

    int i = blockIdx.x * blockDim.x + threadIdx.x;
    if (i >= NP) return;
    float2 p = ((const float2*)pos)[i];
    int ix = (int)ceilf((p.x - qx) / hM);
    int iy = (int)ceilf((p.y - qy) / hM);
    ix = min(max(ix, 0), GRIDW - 1);
    iy = min(max(iy, 0), GRIDW - 1);
    int lin = ix + GRIDW * iy;
    int slot = atomicAdd(&g_cellCount[lin], 1);
    if (slot < CAP)
        g_cellListP[lin * CAP + slot] = make_float4(__int_as_float(i), p.x, p.y, 0.0f);

    // ---- per-particle: t = largest float with fl(sqrt(t)) <= h  (exact) ----
    float h = sup[i];
    float u = __fmul_rn(h, h);
    if (__fsqrt_rn(u) > h) u = __int_as_float(__float_as_int(u) - 1);
    if (__fsqrt_rn(u) > h) u = __int_as_float(__float_as_int(u) - 1);
    if (__fsqrt_rn(u) > h) u = __int_as_float(__float_as_int(u) - 1);
    float un = __int_as_float(__float_as_int(u) + 1);
    if (__fsqrt_rn(un) <= h) {
        u = un; un = __int_as_float(__float_as_int(u) + 1);
        if (__fsqrt_rn(un) <= h) {
            u = un; un = __int_as_float(__float_as_int(u) + 1);
            if (__fsqrt_rn(un) <= h) u = un;
        }
    }
    g_aux[i] = make_float2(u, __frcp_rn(h));
}

// ------- kernel 3: rank sort, TWO cells per warp (2x MLP on load chain) -----
__global__ void sortK() {
    int base = ((blockIdx.x * blockDim.x + threadIdx.x) >> 5) * 2;
    if (base >= NUM_CELLS) return;
    int lane = threadIdx.x & 31;
    int w0 = base, w1 = base + 1;

    int m0 = min(g_cellCount[w0], KSLOT);
    int m1 = min(g_cellCount[w1], KSLOT);

    float4 e0 = make_float4(0.f, 0.f, 0.f, 0.f);
    float4 e1 = make_float4(0.f, 0.f, 0.f, 0.f);
    int idx0 = 0x7fffffff, idx1 = 0x7fffffff;
    if (lane < m0) { e0 = g_cellListP[w0 * CAP + lane]; idx0 = __float_as_int(e0.x); }
    if (lane < m1) { e1 = g_cellListP[w1 * CAP + lane]; idx1 = __float_as_int(e1.x); }

    int r0 = 0, r1 = 0;
    for (int j = 0; j < m0; j++) r0 += (__shfl_sync(FULLM, idx0, j) < idx0);
    for (int j = 0; j < m1; j++) r1 += (__shfl_sync(FULLM, idx1, j) < idx1);

    if (lane == 0) { g_tabCnt[w0] = m0; g_tabCnt[w1] = m1; }
    if (lane < m0) g_tab[w0 * KSLOT + r0] = e0;
    if (lane < m1) g_tab[w1 * KSLOT + r1] = e1;
}

__device__ __forceinline__ float sqrt_approx(float x) {
    float r;
    asm("sqrt.approx.f32 %0, %1;" : "=f"(r) : "f"(x));
    return r;
}

// ------- kernel 4: warp-per-cell neighbor search (R14 + inf-padded preload) --
__global__ void searchK(float* __restrict__ out) {
    int w = (blockIdx.x * blockDim.x + threadIdx.x) >> 5;   // warp id = cell
    if (w >= NUM_CELLS) return;
    int lane = threadIdx.x & 31;
    const float INF = __int_as_float(0x7f800000);

    // ---- stencil setup (once per cell) ----
    int c = NUM_CELLS, m = 0;
    if (lane < 9) {
        int dxo = lane / 3 - 1;
        int dyo = lane % 3 - 1;
        int cc = w + dxo + GRIDW * dyo;
        cc = min(max(cc, 0), NUM_CELLS);
        c = cc;
        m = g_tabCnt[cc];
    }
    int incl = m;
#pragma unroll
    for (int d = 1; d < 16; d <<= 1) {
        int v = __shfl_up_sync(FULLM, incl, d);
        if (lane >= d) incl += v;
    }
    int pref = incl - m;
    int T = __shfl_sync(FULLM, incl, 8);

    int qcnt = __shfl_sync(FULLM, m, 4);      // center cell = this cell's queries
    if (qcnt == 0) return;

    int p1 = __shfl_sync(FULLM, pref, 1);
    int p2 = __shfl_sync(FULLM, pref, 2);
    int p3 = __shfl_sync(FULLM, pref, 3);
    int p4 = __shfl_sync(FULLM, pref, 4);
    int p5 = __shfl_sync(FULLM, pref, 5);
    int p6 = __shfl_sync(FULLM, pref, 6);
    int p7 = __shfl_sync(FULLM, pref, 7);
    int p8 = __shfl_sync(FULLM, pref, 8);

    // ---- query data (direct load) ----
    float4 qe = make_float4(0.f, 0.f, 0.f, 0.f);
    float tL = 0.0f, rhL = 0.0f;
    int qidl = 0;
    if (lane < qcnt) {
        qe = g_cellListP[w * CAP + lane];
        qidl = __float_as_int(qe.x);
        float2 aux = __ldg(&g_aux[qidl]);     // parallel prefetch {t, 1/h}
        tL = aux.x; rhL = aux.y;
    }

    // ---- preload candidates, INF-padded (padding lanes can never pass) ----
    float4 e0 = make_float4(0.f, INF, INF, 0.f);
    float4 e1 = make_float4(0.f, INF, INF, 0.f);
    {
        int t = lane;
        int o = (t >= p1) + (t >= p2) + (t >= p3) + (t >= p4) +
                (t >= p5) + (t >= p6) + (t >= p7) + (t >= p8);
        int cc = __shfl_sync(FULLM, c, o);
        int po = __shfl_sync(FULLM, pref, o);
        if (t < T) e0 = g_tab[cc * KSLOT + (t - po)];
    }
    if (T > 32) {
        int t = lane + 32;
        int o = (t >= p1) + (t >= p2) + (t >= p3) + (t >= p4) +
                (t >= p5) + (t >= p6) + (t >= p7) + (t >= p8);
        int cc = __shfl_sync(FULLM, c, o);
        int po = __shfl_sync(FULLM, pref, o);
        if (t < T) e1 = g_tab[cc * KSLOT + (t - po)];
    }
    float n0 = (float)__float_as_int(e0.x);
    float n1 = (float)__float_as_int(e1.x);

    float* outN = out;                              // (N, 64) neighbor indices
    float* outC = out + (size_t)NP * MAXN;          // (N,)    counts
    float* outR = outC + NP;                        // (N, 64) radial

    int myCnt = 0;                                  // this lane's query count

    // ---- per-query loop ----
    for (int q = 0; q < qcnt; q++) {
        float px = __shfl_sync(FULLM, qe.y, q);
        float py = __shfl_sync(FULLM, qe.z, q);
        float tq = __shfl_sync(FULLM, tL, q);
        float rh = __shfl_sync(FULLM, rhL, q);
        int  qid = __shfl_sync(FULLM, qidl, q);
        int  rbase = qid << 6;                      // 32-bit row offset
        float* pN = outN + rbase;
        float* pR = outR + rbase;

        int cnt;
        // chunk 0 — bare d2 <= tq predicate (inf-padding handles inactivity)
        {
            float dx = __fsub_rn(e0.y, px);
            float dy = __fsub_rn(e0.z, py);
            float d2 = __fadd_rn(__fmul_rn(dx, dx), __fmul_rn(dy, dy));
            bool ok = d2 <= tq;
            unsigned bal = __ballot_sync(FULLM, ok);
            int slot = __popc(bal & ((1u << lane) - 1u));
            if (ok) {
                __stcs(&pN[slot], n0);
                __stcs(&pR[slot], __fmul_rn(sqrt_approx(d2), rh));
            }
            cnt = __popc(bal);
        }
        // chunk 1
        if (T > 32) {
            float dx = __fsub_rn(e1.y, px);
            float dy = __fsub_rn(e1.z, py);
            float d2 = __fadd_rn(__fmul_rn(dx, dx), __fmul_rn(dy, dy));
            bool ok = d2 <= tq;
            unsigned bal = __ballot_sync(FULLM, ok);
            int slot = cnt + __popc(bal & ((1u << lane) - 1u));
            if (ok) {
                __stcs(&pN[slot], n1);
                __stcs(&pR[slot], __fmul_rn(sqrt_approx(d2), rh));
            }
            cnt += __popc(bal);
        }
        // rare: T > 64
        for (int tb = 64; tb < T; tb += 32) {
            int t = tb + lane;
            bool act = t < T;
            int o = (t >= p1) + (t >= p2) + (t >= p3) + (t >= p4) +
                    (t >= p5) + (t >= p6) + (t >= p7) + (t >= p8);
            int cc = __shfl_sync(FULLM, c, o);
            int po = __shfl_sync(FULLM, pref, o);
            float nidx = 0.0f, d2 = 0.0f;
            bool ok = false;
            if (act) {
                float4 e = g_tab[cc * KSLOT + (t - po)];
                float dx = __fsub_rn(e.y, px);
                float dy = __fsub_rn(e.z, py);
                d2 = __fadd_rn(__fmul_rn(dx, dx), __fmul_rn(dy, dy));
                nidx = (float)__float_as_int(e.x);
                ok = d2 <= tq;
            }
            unsigned bal = __ballot_sync(FULLM, ok);
            int slot = cnt + __popc(bal & ((1u << lane) - 1u));
            if (ok && slot < MAXN) {
                __stcs(&pN[slot], nidx);
                __stcs(&pR[slot], __fmul_rn(sqrt_approx(d2), rh));
            }
            cnt += __popc(bal);
        }
        // tail fill: unrolled two predicated steps (tail length <= 64)
        int start = min(cnt, MAXN);
        int k0 = start + lane;
        if (k0 < MAXN) {
            __stcs(&pN[k0], -1.0f);
            __stcs(&pR[k0], 0.0f);
        }
        int k1 = k0 + 32;
        if (k1 < MAXN) {
            __stcs(&pN[k1], -1.0f);
            __stcs(&pR[k1], 0.0f);
        }
        if (q == lane) myCnt = cnt;                 // defer count store
    }
    if (lane < qcnt) __stcs(&outC[qidl], (float)myCnt);
}

// ---------------- launch ------------------------------------------------------
extern "C" void kernel_launch(void* const* d_in, const int* in_sizes, int n_in,
                              void* d_out, int out_size) {
    const float* pos = (const float*)d_in[0];   // (N, 2) float32
    const float* sup = (const float*)d_in[1];   // (N,)   float32
    float* out = (float*)d_out;

    initRedK<<<256, 256>>>(pos, sup);
    binK<<<NP / 256, 256>>>(pos, sup);
    sortK<<<(NUM_CELLS / 2 * 32) / 256, 256>>>();
    searchK<<<(NUM_CELLS * 32) / 256, 256>>>(out);
}